// round 13
// baseline (speedup 1.0000x reference)
#include <cuda_runtime.h>
#include <cuda_fp16.h>
#include <math.h>
#include <stdint.h>

#define B_   1024
#define T_   100
#define XD_  38
#define H_   500
#define ZD_  16
#define L_   3
#define G3H  1500
#define HP   512
#define MT_G 16
#define NT_G 8
#define CH_  8
#define AIMG 8192
#define BIMG 8192
#define RROWS 32
#define NCTA_P 256
#define SMEM_P   84992
#define SMEM_RC  65536

// ----------------------------- device scratch --------------------------------
__device__ __align__(1024) float   g_h[(size_t)2*B_*HP];
__device__ __align__(1024) uint8_t g_Ah[(size_t)2*2*MT_G*CH_*AIMG];   // [gru][par][mt][ch]
__device__ __align__(1024) uint8_t g_Bw[(size_t)2*NT_G*3*CH_*BIMG];   // [gru][nt][gate][ch]
__device__ __align__(1024) uint8_t g_Xs[(size_t)T_*MT_G*AIMG];        // x(t) images [t][mt]
__device__ __align__(1024) uint8_t g_Bxw[(size_t)NT_G*3*BIMG];        // Wih_q images [nt][gate]
__device__ __align__(1024) float   g_hist[(size_t)B_*T_*HP];
__device__ float g_part[2][NT_G][B_][32];
__device__ unsigned g_tick[2][MT_G];
__device__ float g_uhat[L_*ZD_];
__device__ unsigned g_bar_count;
__device__ volatile unsigned g_bar_gen;

// ----------------------------- helpers ---------------------------------------
__device__ __forceinline__ float sigmoidf_(float x){ return 1.0f/(1.0f+expf(-x)); }
__device__ __forceinline__ float softplusf_(float x){ return (x>20.0f)? x : log1pf(expf(x)); }
__device__ __forceinline__ uint32_t swz128(uint32_t off){ return off ^ ((off>>3)&0x70); }

__device__ __forceinline__ size_t a_img(int gru,int par,int mt,int ch){
    return ((((size_t)gru*2 + par)*MT_G + mt)*CH_ + ch)*AIMG;
}
__device__ __forceinline__ size_t b_img(int gru,int nt,int gate,int ch){
    return ((((size_t)gru*NT_G + nt)*3 + gate)*CH_ + ch)*BIMG;
}
__device__ __forceinline__ uint32_t smem_u32(const void* p){
    uint32_t a;
    asm("{ .reg .u64 t; cvta.to.shared.u64 t, %1; cvt.u32.u64 %0, t; }" : "=r"(a) : "l"(p));
    return a;
}
__device__ __forceinline__ void cp_async16(uint32_t dst, const void* src){
    asm volatile("cp.async.cg.shared.global [%0], [%1], 16;" :: "r"(dst), "l"(src));
}
__device__ __forceinline__ void cp_commit(){ asm volatile("cp.async.commit_group;" ::: "memory"); }
template<int N>
__device__ __forceinline__ void cp_wait(){ asm volatile("cp.async.wait_group %0;" :: "n"(N) : "memory"); }
__device__ __forceinline__ void ldsm_x4(uint32_t& r0, uint32_t& r1, uint32_t& r2, uint32_t& r3, uint32_t addr){
    asm volatile("ldmatrix.sync.aligned.m8n8.x4.shared.b16 {%0,%1,%2,%3}, [%4];"
                 : "=r"(r0), "=r"(r1), "=r"(r2), "=r"(r3) : "r"(addr));
}
__device__ __forceinline__ void mma_fp16(float* c, const uint32_t* a, const uint32_t* b){
    asm volatile("mma.sync.aligned.m16n8k16.row.col.f32.f16.f16.f32 "
                 "{%0,%1,%2,%3}, {%4,%5,%6,%7}, {%8,%9}, {%0,%1,%2,%3};"
                 : "+f"(c[0]), "+f"(c[1]), "+f"(c[2]), "+f"(c[3])
                 : "r"(a[0]), "r"(a[1]), "r"(a[2]), "r"(a[3]), "r"(b[0]), "r"(b[1]));
}
__device__ __forceinline__ void grid_barrier(unsigned &gen){
    __syncthreads();
    gen++;
    if (threadIdx.x == 0){
        __threadfence();
        unsigned prev = atomicAdd(&g_bar_count, 1u);
        if (prev == gen*NCTA_P - 1u){
            __threadfence();
            g_bar_gen = gen;
        } else {
            while (g_bar_gen < gen) __nanosleep(64);
        }
    }
    __syncthreads();
    __threadfence();
}

// ----------------------------- setup launch 1: init --------------------------
__global__ void init_kernel(float* __restrict__ out_ld,
                            const float* __restrict__ fu, const float* __restrict__ fw){
    size_t i = (size_t)blockIdx.x*blockDim.x + threadIdx.x;
    size_t stride = (size_t)gridDim.x*blockDim.x;
    float4* h4 = (float4*)g_h;
    for (size_t k=i; k<sizeof(g_h)/16;  k+=stride) h4[k] = make_float4(0,0,0,0);
    uint4* p;
    p = (uint4*)g_Ah;  for (size_t k=i; k<sizeof(g_Ah)/16;  k+=stride) p[k] = make_uint4(0,0,0,0);
    p = (uint4*)g_Bw;  for (size_t k=i; k<sizeof(g_Bw)/16;  k+=stride) p[k] = make_uint4(0,0,0,0);
    p = (uint4*)g_Xs;  for (size_t k=i; k<sizeof(g_Xs)/16;  k+=stride) p[k] = make_uint4(0,0,0,0);
    p = (uint4*)g_Bxw; for (size_t k=i; k<sizeof(g_Bxw)/16; k+=stride) p[k] = make_uint4(0,0,0,0);
    for (size_t k=i; k<B_; k+=stride) out_ld[k]=0.f;
    if (i < 2*MT_G) ((unsigned*)g_tick)[i] = 0u;
    if (i == 0){ g_bar_count = 0; g_bar_gen = 0; }
    if (i < L_){
        int k = (int)i;
        float wu=0.f, ww=0.f;
        for (int j=0;j<ZD_;j++){ wu += fw[k*ZD_+j]*fu[k*ZD_+j]; ww += fw[k*ZD_+j]*fw[k*ZD_+j]; }
        float m = -1.0f + softplusf_(wu);
        float scale = (m - wu)/(ww + 1e-6f);
        for (int j=0;j<ZD_;j++) g_uhat[k*ZD_+j] = fu[k*ZD_+j] + scale*fw[k*ZD_+j];
    }
}

// ----------------------------- setup launch 2: stage both Whh ----------------
__global__ void stage_whh(const float* __restrict__ Wq, const float* __restrict__ Wp){
    int idx = blockIdx.x*blockDim.x + threadIdx.x;
    if (idx >= 2*G3H*H_) return;
    int gru = idx / (G3H*H_);
    int rem = idx - gru*(G3H*H_);
    int n = rem / H_, k = rem - n*H_;
    float v = (gru ? Wp : Wq)[n*H_ + k];
    int gate = n / 500, j = n - gate*500;
    int nt = j>>6, r = j&63, ch = k>>6, c = k&63;
    *(__half*)(g_Bw + b_img(gru,nt,gate,ch) + swz128((uint32_t)(r*128 + c*2))) = __float2half_rn(v);
}

// ----------------------------- setup launch 3: stage x + Wih_q ---------------
__global__ void stage_x_wih(const float* __restrict__ x, const float* __restrict__ Wih_q){
    int idx = blockIdx.x*blockDim.x + threadIdx.x;
    const int NX = B_*T_*XD_;
    if (idx < NX){
        int m = idx / XD_, d = idx - m*XD_;
        int b = m / T_, t = m - b*T_;
        int mt = b>>6, r = b&63;
        uint32_t sw = swz128((uint32_t)(r*128 + d*2));
        *(__half*)(g_Xs + ((size_t)t*MT_G + mt)*AIMG + sw) = __float2half_rn(x[idx]);
    } else if (idx < NX + G3H*XD_){
        int e = idx - NX;
        int n = e / XD_, d = e - n*XD_;
        int gate = n / 500, j = n - gate*500;
        int nt = j>>6, r = j&63;
        *(__half*)(g_Bxw + ((size_t)nt*3 + gate)*BIMG + swz128((uint32_t)(r*128 + d*2))) =
            __float2half_rn(Wih_q[n*XD_ + d]);
    }
}

// ----------------------------- persistent stepped kernel ---------------------
// grid (8, 32): y<16 -> p-role (gru=1), y>=16 -> q-role (gru=0).
// iteration it: p runs t=it (it>=0), q runs t=it+1 (it+1<T). Grid barrier per it.
// q folds x(t)-projection in as a 9th K chunk (gate n into separate accX).
// The LAST q CTA per mt (atomic ticket) computes mu/std/flows/z(t) in its tail.
__global__ __launch_bounds__(256,2)
void gru_persist(const float* __restrict__ eps,
                 const float* __restrict__ Wihp,
                 const float* __restrict__ bihp, const float* __restrict__ bhhp,
                 const float* __restrict__ bihq, const float* __restrict__ bhhq,
                 const float* __restrict__ Wqm, const float* __restrict__ bqm,
                 const float* __restrict__ Wqs, const float* __restrict__ bqs,
                 const float* __restrict__ fw, const float* __restrict__ fb,
                 float* __restrict__ out_z, float* __restrict__ out_mu,
                 float* __restrict__ out_std, float* __restrict__ out_ld){
    int role = blockIdx.y >> 4;
    int gru  = role ? 0 : 1;            // 1 = p, 0 = q
    int nt = blockIdx.x, mt = blockIdx.y & 15;

    extern __shared__ uint8_t smem_raw[];
    uint8_t* tiles = (uint8_t*)(((uintptr_t)smem_raw + 1023) & ~(uintptr_t)1023);
    uint32_t sbase = smem_u32(tiles);
    // statics above the 2x32KB tile buffers
    float* zzS  = (float*)(tiles + 65536);   // p: [64][17] per-step
    float* wpS  = (float*)(tiles + 69888);   // p: [16][192] static
    float* bspS = (float*)(tiles + 82176);   // p: [4][64]  static
    float* bq4S = (float*)(tiles + 65536);   // q: [4][64]  static
    float* WqS  = (float*)(tiles + 66560);   // q: [64][32] static
    float* WzS  = (float*)(tiles + 74752);   // q: [16][32] static
    int*   winF = (int*)  (tiles + 76800);   // q: winner flag

    int tid = threadIdx.x, wid = tid>>5, lane = tid&31;
    int wm = wid & 1, wn = wid >> 1;

    // ---- one-time staging of time-invariant data ----
    if (!gru){
        {
            int q4 = tid >> 6, jj = tid & 63;
            int j = nt*64 + jj;
            float v = 0.f;
            if (j < 500){
                if (q4 == 0) v = bihq[j]       + bhhq[j];
                else if (q4 == 1) v = bihq[500+j]  + bhhq[500+j];
                else if (q4 == 2) v = bihq[1000+j];
                else v = bhhq[1000+j];
            }
            bq4S[q4*64 + jj] = v;
        }
        for (int idx = tid; idx < 64*32; idx += 256){
            int j = idx >> 5, o = idx & 31;
            int gj = nt*64 + j;
            float v = 0.f;
            if (gj < H_)
                v = (o < 16) ? Wqm[o*(H_+ZD_) + gj] : Wqs[(o-16)*(H_+ZD_) + gj];
            WqS[j*32+o] = v;
        }
        for (int idx = tid; idx < 16*32; idx += 256){
            int d = idx >> 5, o = idx & 31;
            WzS[idx] = (o < 16) ? Wqm[o*(H_+ZD_) + H_ + d]
                                : Wqs[(o-16)*(H_+ZD_) + H_ + d];
        }
    } else {
        for (int idx = tid; idx < ZD_*192; idx += 256){
            int d = idx & 15, col = idx >> 4;
            int gg = col >> 6, jj = col & 63;
            int j = nt*64 + jj;
            wpS[d*192 + col] = (j < 500) ? Wihp[((size_t)(gg*500 + j))*ZD_ + d] : 0.f;
        }
        {
            int q4 = tid >> 6, jj = tid & 63;
            int j = nt*64 + jj;
            float v = 0.f;
            if (j < 500){
                if (q4 == 0) v = bihp[j]       + bhhp[j];
                else if (q4 == 1) v = bihp[500+j]  + bhhp[500+j];
                else if (q4 == 2) v = bihp[1000+j];
                else v = bhhp[1000+j];
            }
            bspS[q4*64 + jj] = v;
        }
    }
    __syncthreads();

    int g = lane >> 3, l = lane & 7;
    int a_row = wm*32 + (g&1)*8 + l;
    int a_kb  = (g>>1)*16;
    int b_row = wn*16 + (g>>1)*8 + l;
    int b_kb  = (g&1)*16;
    int rr = lane>>2, cc = (lane&3)*2;

    unsigned gen = 0;

    for (int it = -1; it < T_; ++it){
        int t = gru ? it : (it + 1);
        bool active = gru ? (it >= 0) : (it + 1 < T_);
        if (active){
            int par_w = t & 1;
            int par_r = par_w ^ 1;
            int nch = gru ? CH_ : (CH_ + 1);

            auto copy_chunk = [&](int ch, int buf){
                const uint8_t* srcs[4];
                if (ch < CH_){
                    srcs[0] = g_Ah + a_img(gru,par_r,mt,ch);
                    srcs[1] = g_Bw + b_img(gru,nt,0,ch);
                    srcs[2] = g_Bw + b_img(gru,nt,1,ch);
                    srcs[3] = g_Bw + b_img(gru,nt,2,ch);
                } else {
                    srcs[0] = g_Xs  + ((size_t)t*MT_G + mt)*AIMG;
                    srcs[1] = g_Bxw + ((size_t)nt*3 + 0)*BIMG;
                    srcs[2] = g_Bxw + ((size_t)nt*3 + 1)*BIMG;
                    srcs[3] = g_Bxw + ((size_t)nt*3 + 2)*BIMG;
                }
                uint32_t dbase = sbase + buf*32768;
#pragma unroll
                for (int r=0;r<8;r++){
                    int idx = r*256 + tid;
                    int img = idx >> 9;
                    int off = (idx & 511)*16;
                    cp_async16(dbase + img*8192 + off, srcs[img] + off);
                }
            };

            copy_chunk(0,0); cp_commit();

            if (gru){
                // p prologue: just load z(t) (written by q winner last iteration)
                for (int idx = tid; idx < 64*16; idx += 256){
                    int r = idx >> 4, d = idx & 15;
                    zzS[r*17 + d] = __ldcg(&out_z[((size_t)(mt*64+r)*T_ + t)*ZD_ + d]);
                }
            }
            __syncthreads();

            float acc[3][2][2][4];
            float accX[2][2][4];
#pragma unroll
            for (int a=0;a<3;a++)
#pragma unroll
                for (int i=0;i<2;i++)
#pragma unroll
                    for (int j=0;j<2;j++)
#pragma unroll
                        for (int c=0;c<4;c++) acc[a][i][j][c]=0.f;
#pragma unroll
            for (int i=0;i<2;i++)
#pragma unroll
                for (int j=0;j<2;j++)
#pragma unroll
                    for (int c=0;c<4;c++) accX[i][j][c]=0.f;

            for (int ch=0; ch<nch; ch++){
                if (ch+1 < nch){ copy_chunk(ch+1,(ch+1)&1); cp_commit(); cp_wait<1>(); }
                else cp_wait<0>();
                __syncthreads();

                uint32_t Ahi_b = sbase + (ch&1)*32768;
                uint32_t Bb    = Ahi_b + 8192;
                bool isx = (ch == CH_);

#pragma unroll
                for (int s=0; s<4; s++){
                    uint32_t Ah[2][4], Bf[3][2][2];
                    uint32_t a_off = swz128((uint32_t)(a_row*128 + s*32 + a_kb));
                    uint32_t b_off = swz128((uint32_t)(b_row*128 + s*32 + b_kb));
#pragma unroll
                    for (int mi=0; mi<2; mi++)
                        ldsm_x4(Ah[mi][0],Ah[mi][1],Ah[mi][2],Ah[mi][3], Ahi_b + a_off + mi*2048);
#pragma unroll
                    for (int g3=0; g3<3; g3++){
                        uint32_t r0,r1,r2,r3;
                        ldsm_x4(r0,r1,r2,r3, Bb + g3*8192 + b_off);
                        Bf[g3][0][0]=r0; Bf[g3][0][1]=r1; Bf[g3][1][0]=r2; Bf[g3][1][1]=r3;
                    }
#pragma unroll
                    for (int mi=0; mi<2; mi++)
#pragma unroll
                        for (int ni=0; ni<2; ni++){
                            mma_fp16(acc[0][mi][ni], Ah[mi], Bf[0][ni]);
                            mma_fp16(acc[1][mi][ni], Ah[mi], Bf[1][ni]);
                            if (isx) mma_fp16(accX[mi][ni],   Ah[mi], Bf[2][ni]);
                            else     mma_fp16(acc[2][mi][ni], Ah[mi], Bf[2][ni]);
                        }
                }
                __syncthreads();
            }

            // -------- epilogue: GRU combine in registers --------
            float* hqS = (float*)tiles;              // q: [64][65]
#pragma unroll
            for (int mi=0; mi<2; mi++){
#pragma unroll
                for (int hh=0; hh<2; hh++){
                    int mrow = wm*32 + mi*16 + hh*8 + rr;
                    int b = mt*64 + mrow;
                    float zr[ZD_];
                    if (gru){
#pragma unroll
                        for (int d=0; d<ZD_; d++) zr[d] = zzS[mrow*17 + d];
                    }
#pragma unroll
                    for (int ni=0; ni<2; ni++){
                        int jj = wn*16 + ni*8 + cc;
                        int j = nt*64 + jj;
                        if (j >= 500){
                            if (!gru){ hqS[mrow*65+jj] = 0.f; hqS[mrow*65+jj+1] = 0.f; }
                            continue;
                        }
                        float xw0[3], xw1[3];
                        if (!gru){
                            xw0[0] = accX ? 0.f : 0.f; // placeholder (overwritten below)
                            // q: x-projection already inside accumulators
                            xw0[0] = bq4S[0*64 + jj];      xw1[0] = bq4S[0*64 + jj + 1];
                            xw0[1] = bq4S[1*64 + jj];      xw1[1] = bq4S[1*64 + jj + 1];
                            xw0[2] = accX[mi][ni][hh*2+0] + bq4S[2*64 + jj];
                            xw1[2] = accX[mi][ni][hh*2+1] + bq4S[2*64 + jj + 1];
                        } else {
#pragma unroll
                            for (int g3=0; g3<3; g3++){
                                float s0 = bspS[g3*64 + jj];
                                float s1 = bspS[g3*64 + jj + 1];
#pragma unroll
                                for (int d=0; d<ZD_; d++){
                                    float zv = zr[d];
                                    s0 = fmaf(zv, wpS[d*192 + g3*64 + jj],     s0);
                                    s1 = fmaf(zv, wpS[d*192 + g3*64 + jj + 1], s1);
                                }
                                xw0[g3] = s0; xw1[g3] = s1;
                            }
                        }
                        float bn0 = gru ? bspS[3*64 + jj]     : bq4S[3*64 + jj];
                        float bn1 = gru ? bspS[3*64 + jj + 1] : bq4S[3*64 + jj + 1];
                        float aR0 = acc[0][mi][ni][hh*2+0], aR1 = acc[0][mi][ni][hh*2+1];
                        float aZ0 = acc[1][mi][ni][hh*2+0], aZ1 = acc[1][mi][ni][hh*2+1];
                        float aN0 = acc[2][mi][ni][hh*2+0], aN1 = acc[2][mi][ni][hh*2+1];

                        float2 hp = *(float2*)&g_h[(size_t)(gru*1024 + b)*HP + j];
                        float r0 = sigmoidf_(xw0[0] + aR0);
                        float r1 = sigmoidf_(xw1[0] + aR1);
                        float z0 = sigmoidf_(xw0[1] + aZ0);
                        float z1 = sigmoidf_(xw1[1] + aZ1);
                        float n0 = tanhf(xw0[2] + r0*(aN0 + bn0));
                        float n1 = tanhf(xw1[2] + r1*(aN1 + bn1));
                        float h0 = (1.f - z0)*n0 + z0*hp.x;
                        float h1 = (1.f - z1)*n1 + z1*hp.y;

                        *(float2*)&g_h[(size_t)(gru*1024 + b)*HP + j] = make_float2(h0, h1);

                        __half2 hi2 = __floats2half2_rn(h0, h1);
                        uint32_t sw = swz128((uint32_t)(mrow*128 + (j&63)*2));
                        *(__half2*)(g_Ah + a_img(gru, par_w, mt, j>>6) + sw) = hi2;

                        if (gru){
                            *(float2*)&g_hist[((size_t)b*T_ + t)*HP + j] = make_float2(h0, h1);
                        } else {
                            hqS[mrow*65+jj]   = h0;
                            hqS[mrow*65+jj+1] = h1;
                        }
                    }
                }
            }

            // -------- q role: partials + (winner) z/flows --------
            if (!gru){
                __syncthreads();
                for (int idx = tid; idx < 64*32; idx += 256){
                    int b = idx >> 5, o = idx & 31;
                    float s = 0.f;
#pragma unroll
                    for (int j=0;j<64;j++)
                        s = fmaf(hqS[b*65+j], WqS[j*32+o], s);
                    __stcg(&g_part[t&1][nt][mt*64+b][o], s);
                }
                __threadfence();
                __syncthreads();
                if (tid == 0){
                    unsigned v = atomicAdd(&g_tick[t&1][mt], 1u);
                    *winF = (v == 7u);
                    if (v == 7u) atomicExch(&g_tick[t&1][mt], 0u);
                }
                __syncthreads();
                if (*winF){
                    float* zwS = (float*)(tiles + 20480);   // [64][16]
                    float* muS = (float*)(tiles + 24576);   // [64][16]
                    float* sdS = (float*)(tiles + 28672);   // [64][16]
                    for (int idx = tid; idx < 64*16; idx += 256){
                        int r = idx >> 4, d = idx & 15;
                        zwS[idx] = (t==0) ? 0.f
                                 : __ldcg(&out_z[((size_t)(mt*64+r)*T_ + (t-1))*ZD_ + d]);
                    }
                    __syncthreads();
                    for (int idx = tid; idx < 64*32; idx += 256){
                        int b = idx >> 5, o = idx & 31;
                        int gb = mt*64 + b;
                        float s = 0.f;
#pragma unroll
                        for (int q8 = 0; q8 < NT_G; q8++)
                            s += __ldcg(&g_part[t&1][q8][gb][o]);
#pragma unroll
                        for (int d = 0; d < ZD_; d++) s = fmaf(zwS[b*16+d], WzS[d*32+o], s);
                        if (o < 16){
                            float mu = s + bqm[o];
                            muS[b*16+o] = mu;
                            out_mu[((size_t)gb*T_+t)*ZD_+o] = mu;
                        } else {
                            int oj = o - 16;
                            float sd = softplusf_(s + bqs[oj]) + 1e-4f;
                            sdS[b*16+oj] = sd;
                            out_std[((size_t)gb*T_+t)*ZD_+oj] = sd;
                        }
                    }
                    __syncthreads();
                    if (tid < 64){
                        int b = tid, gb = mt*64 + b;
                        float z[ZD_];
#pragma unroll
                        for (int d=0; d<ZD_; d++)
                            z[d] = muS[b*16+d] + eps[((size_t)gb*T_+t)*ZD_+d]*sdS[b*16+d];
                        float ld = 0.f;
#pragma unroll
                        for (int k=0;k<L_;k++){
                            float dot = 0.f;
                            for (int i=0;i<ZD_;i++) dot = fmaf(z[i], fw[k*ZD_+i], dot);
                            float hh = tanhf(dot + fb[k]);
                            float psiu = 0.f;
                            for (int i=0;i<ZD_;i++){
                                z[i] += g_uhat[k*ZD_+i]*hh;
                                psiu = fmaf((1.f - hh*hh)*fw[k*ZD_+i], g_uhat[k*ZD_+i], psiu);
                            }
                            ld += logf(fabsf(1.f + psiu) + 1e-6f);
                        }
#pragma unroll
                        for (int d=0; d<ZD_; d++)
                            out_z[((size_t)gb*T_+t)*ZD_+d] = z[d];
                        out_ld[gb] += ld;
                    }
                }
            }
        }
        grid_barrier(gen);
    }
}

// ----------------------------- post-loop: all reconstructions ----------------
__global__ __launch_bounds__(256)
void recon_all(const float* __restrict__ Wpm, const float* __restrict__ bpm,
               const float* __restrict__ Wps, const float* __restrict__ bps,
               float* __restrict__ out_rm, float* __restrict__ out_rs){
    extern __shared__ float hs[];    // [RROWS][HP]
    int m0 = blockIdx.x * RROWS;
    int tid = threadIdx.x, w = tid>>5, lane = tid&31;
#pragma unroll
    for (int k=0;k<RROWS*128/256;k++){
        int idx = k*256 + tid;
        int r = idx >> 7, q4 = idx & 127;
        ((float4*)&hs[r*HP])[q4] = ((const float4*)&g_hist[(size_t)(m0+r)*HP])[q4];
    }
    __syncthreads();
    for (int o = w; o < 2*XD_; o += 8){
        int d = (o < XD_) ? o : o - XD_;
        const float* Wrow = ((o < XD_) ? Wpm : Wps) + (size_t)d*H_;
        for (int r=0;r<RROWS;r++){
            float acc = 0.f;
            for (int i=lane; i<H_; i+=32) acc = fmaf(hs[r*HP+i], Wrow[i], acc);
#pragma unroll
            for (int off=16; off; off>>=1) acc += __shfl_down_sync(0xFFFFFFFFu, acc, off);
            if (lane == 0){
                size_t oidx = (size_t)(m0+r)*XD_ + d;
                if (o < XD_) out_rm[oidx] = acc + bpm[d];
                else         out_rs[oidx] = softplusf_(acc + bps[d]) + 1e-4f;
            }
        }
    }
}

// ----------------------------- launcher --------------------------------------
extern "C" void kernel_launch(void* const* d_in, const int* in_sizes, int n_in,
                              void* d_out, int out_size){
    const float* x     = (const float*)d_in[0];
    const float* eps   = (const float*)d_in[1];
    const float* Wih_q = (const float*)d_in[2];
    const float* Whh_q = (const float*)d_in[3];
    const float* bih_q = (const float*)d_in[4];
    const float* bhh_q = (const float*)d_in[5];
    const float* Wqm   = (const float*)d_in[6];
    const float* bqm   = (const float*)d_in[7];
    const float* Wqs   = (const float*)d_in[8];
    const float* bqs   = (const float*)d_in[9];
    const float* Wih_p = (const float*)d_in[10];
    const float* Whh_p = (const float*)d_in[11];
    const float* bih_p = (const float*)d_in[12];
    const float* bhh_p = (const float*)d_in[13];
    const float* Wpm   = (const float*)d_in[14];
    const float* bpm   = (const float*)d_in[15];
    const float* Wps   = (const float*)d_in[16];
    const float* bps   = (const float*)d_in[17];
    const float* fu    = (const float*)d_in[18];
    const float* fw    = (const float*)d_in[19];
    const float* fb    = (const float*)d_in[20];

    float* out = (float*)d_out;
    float* out_rm  = out;
    float* out_rs  = out_rm  + (size_t)B_*T_*XD_;
    float* out_z   = out_rs  + (size_t)B_*T_*XD_;
    float* out_mu  = out_z   + (size_t)B_*T_*ZD_;
    float* out_std = out_mu  + (size_t)B_*T_*ZD_;
    float* out_ld  = out_std + (size_t)B_*T_*ZD_;

    cudaFuncSetAttribute(gru_persist, cudaFuncAttributeMaxDynamicSharedMemorySize, SMEM_P);
    cudaFuncSetAttribute(recon_all,   cudaFuncAttributeMaxDynamicSharedMemorySize, SMEM_RC);

    init_kernel<<<1024,256>>>(out_ld, fu, fw);
    stage_whh<<<(2*G3H*H_+255)/256,256>>>(Whh_q, Whh_p);
    stage_x_wih<<<(B_*T_*XD_ + G3H*XD_ + 255)/256,256>>>(x, Wih_q);

    dim3 pq_grid(NT_G, 32);   // 8 x 32 = 256 CTAs, 2/SM -> all resident
    gru_persist<<<pq_grid,256,SMEM_P>>>(eps, Wih_p, bih_p, bhh_p, bih_q, bhh_q,
                                        Wqm, bqm, Wqs, bqs, fw, fb,
                                        out_z, out_mu, out_std, out_ld);

    recon_all<<<(B_*T_)/RROWS,256,SMEM_RC>>>(Wpm, bpm, Wps, bps, out_rm, out_rs);
}

// round 14
// speedup vs baseline: 1.1842x; 1.1842x over previous
#include <cuda_runtime.h>
#include <cuda_fp16.h>
#include <math.h>
#include <stdint.h>

#define B_   1024
#define T_   100
#define XD_  38
#define H_   500
#define ZD_  16
#define L_   3
#define G3H  1500
#define HP   512
#define NG   1536
#define MT_G 16
#define NT_G 8
#define CH_  8
#define AIMG 8192
#define BIMG 8192
#define GXMT 800
#define GXNT 24
#define RROWS 32
#define NCTA_P 256
#define SMEM_P   87040
#define SMEM_GX  25600
#define SMEM_RC  65536

// ----------------------------- device scratch --------------------------------
__device__ __align__(1024) float   g_h[(size_t)2*B_*HP];
__device__ __align__(1024) uint8_t g_Ah[(size_t)2*2*MT_G*CH_*AIMG];   // [gru][par][mt][ch]
__device__ __align__(1024) uint8_t g_Bw[(size_t)2*NT_G*3*CH_*BIMG];   // [gru][nt][gate][ch]
__device__ __align__(1024) uint8_t g_Ax[(size_t)GXMT*16384];          // [mt]
__device__ __align__(1024) uint8_t g_Bx[(size_t)GXNT*BIMG];
__device__ __align__(1024) __half  g_Gx[(size_t)B_*T_*NG];
__device__ __align__(1024) float   g_hist[(size_t)B_*T_*HP];
__device__ float g_part[2][NT_G][B_][32];
__device__ float g_uhat[L_*ZD_];
__device__ unsigned g_bar_count;
__device__ volatile unsigned g_bar_gen;

// ----------------------------- helpers ---------------------------------------
// sigmoid(x) = 0.5*tanh(x/2)+0.5  -> single MUFU.TANH on sm_75+ (exact identity)
__device__ __forceinline__ float sigmoidf_(float x){ return fmaf(0.5f, tanhf(0.5f*x), 0.5f); }
__device__ __forceinline__ float softplusf_(float x){ return (x>20.0f)? x : log1pf(expf(x)); }
__device__ __forceinline__ uint32_t swz128(uint32_t off){ return off ^ ((off>>3)&0x70); }

__device__ __forceinline__ size_t a_img(int gru,int par,int mt,int ch){
    return ((((size_t)gru*2 + par)*MT_G + mt)*CH_ + ch)*AIMG;
}
__device__ __forceinline__ size_t b_img(int gru,int nt,int gate,int ch){
    return ((((size_t)gru*NT_G + nt)*3 + gate)*CH_ + ch)*BIMG;
}
__device__ __forceinline__ uint32_t smem_u32(const void* p){
    uint32_t a;
    asm("{ .reg .u64 t; cvta.to.shared.u64 t, %1; cvt.u32.u64 %0, t; }" : "=r"(a) : "l"(p));
    return a;
}
__device__ __forceinline__ void cp_async16(uint32_t dst, const void* src){
    asm volatile("cp.async.cg.shared.global [%0], [%1], 16;" :: "r"(dst), "l"(src));
}
__device__ __forceinline__ void cp_commit(){ asm volatile("cp.async.commit_group;" ::: "memory"); }
template<int N>
__device__ __forceinline__ void cp_wait(){ asm volatile("cp.async.wait_group %0;" :: "n"(N) : "memory"); }
__device__ __forceinline__ void ldsm_x4(uint32_t& r0, uint32_t& r1, uint32_t& r2, uint32_t& r3, uint32_t addr){
    asm volatile("ldmatrix.sync.aligned.m8n8.x4.shared.b16 {%0,%1,%2,%3}, [%4];"
                 : "=r"(r0), "=r"(r1), "=r"(r2), "=r"(r3) : "r"(addr));
}
__device__ __forceinline__ void mma_fp16(float* c, const uint32_t* a, const uint32_t* b){
    asm volatile("mma.sync.aligned.m16n8k16.row.col.f32.f16.f16.f32 "
                 "{%0,%1,%2,%3}, {%4,%5,%6,%7}, {%8,%9}, {%0,%1,%2,%3};"
                 : "+f"(c[0]), "+f"(c[1]), "+f"(c[2]), "+f"(c[3])
                 : "r"(a[0]), "r"(a[1]), "r"(a[2]), "r"(a[3]), "r"(b[0]), "r"(b[1]));
}
__device__ __forceinline__ void grid_barrier(unsigned &gen){
    __syncthreads();
    gen++;
    if (threadIdx.x == 0){
        __threadfence();
        unsigned prev = atomicAdd(&g_bar_count, 1u);
        if (prev == gen*NCTA_P - 1u){
            __threadfence();
            g_bar_gen = gen;
        } else {
            while (g_bar_gen < gen) __nanosleep(64);
        }
    }
    __syncthreads();
    __threadfence();
}

// ----------------------------- setup launch 1: init --------------------------
__global__ void init_kernel(float* __restrict__ out_ld,
                            const float* __restrict__ fu, const float* __restrict__ fw){
    size_t i = (size_t)blockIdx.x*blockDim.x + threadIdx.x;
    size_t stride = (size_t)gridDim.x*blockDim.x;
    float4* h4 = (float4*)g_h;
    for (size_t k=i; k<sizeof(g_h)/16;  k+=stride) h4[k] = make_float4(0,0,0,0);
    uint4* p;
    p = (uint4*)g_Ah; for (size_t k=i; k<sizeof(g_Ah)/16; k+=stride) p[k] = make_uint4(0,0,0,0);
    p = (uint4*)g_Bw; for (size_t k=i; k<sizeof(g_Bw)/16; k+=stride) p[k] = make_uint4(0,0,0,0);
    p = (uint4*)g_Ax; for (size_t k=i; k<sizeof(g_Ax)/16; k+=stride) p[k] = make_uint4(0,0,0,0);
    p = (uint4*)g_Bx; for (size_t k=i; k<sizeof(g_Bx)/16; k+=stride) p[k] = make_uint4(0,0,0,0);
    for (size_t k=i; k<B_; k+=stride) out_ld[k]=0.f;
    if (i == 0){ g_bar_count = 0; g_bar_gen = 0; }
    if (i < L_){
        int k = (int)i;
        float wu=0.f, ww=0.f;
        for (int j=0;j<ZD_;j++){ wu += fw[k*ZD_+j]*fu[k*ZD_+j]; ww += fw[k*ZD_+j]*fw[k*ZD_+j]; }
        float m = -1.0f + softplusf_(wu);
        float scale = (m - wu)/(ww + 1e-6f);
        for (int j=0;j<ZD_;j++) g_uhat[k*ZD_+j] = fu[k*ZD_+j] + scale*fw[k*ZD_+j];
    }
}

// ----------------------------- setup launch 2: stage both Whh ----------------
__global__ void stage_whh(const float* __restrict__ Wq, const float* __restrict__ Wp){
    int idx = blockIdx.x*blockDim.x + threadIdx.x;
    if (idx >= 2*G3H*H_) return;
    int gru = idx / (G3H*H_);
    int rem = idx - gru*(G3H*H_);
    int n = rem / H_, k = rem - n*H_;
    float v = (gru ? Wp : Wq)[n*H_ + k];
    int gate = n / 500, j = n - gate*500;
    int nt = j>>6, r = j&63, ch = k>>6, c = k&63;
    *(__half*)(g_Bw + b_img(gru,nt,gate,ch) + swz128((uint32_t)(r*128 + c*2))) = __float2half_rn(v);
}

// ----------------------------- setup launch 3: stage x + Wih_q ---------------
__global__ void stage_x_wih(const float* __restrict__ x, const float* __restrict__ Wih_q){
    int idx = blockIdx.x*blockDim.x + threadIdx.x;
    const int NX = B_*T_*XD_;
    if (idx < NX){
        int m = idx / XD_, d = idx - m*XD_;
        int mt = m>>7, r = m&127;
        uint32_t sw = swz128((uint32_t)(r*128 + d*2));
        *(__half*)(g_Ax + (size_t)mt*16384 + sw) = __float2half_rn(x[idx]);
    } else if (idx < NX + G3H*XD_){
        int e = idx - NX;
        int n = e / XD_, d = e - n*XD_;
        int gate = n / 500, j = n - gate*500;
        int ni = gate*512 + j;
        int nt = ni>>6, r = ni&63;
        *(__half*)(g_Bx + (size_t)nt*BIMG + swz128((uint32_t)(r*128 + d*2))) =
            __float2half_rn(Wih_q[n*XD_ + d]);
    }
}

// ----------------------------- setup launch 4: Gx = x @ Wih_q^T + bias -------
__global__ __launch_bounds__(256)
void gx_gemm(const float* __restrict__ bih, const float* __restrict__ bhh){
    extern __shared__ uint8_t smem_raw[];
    uint8_t* tiles = (uint8_t*)(((uintptr_t)smem_raw + 1023) & ~(uintptr_t)1023);
    uint32_t sbase = smem_u32(tiles);
    int tid = threadIdx.x, wid = tid>>5, lane = tid&31;
    int nt = blockIdx.x, mt = blockIdx.y;
    int wm = wid & 1, wn = wid >> 1;

    {
        const uint8_t* sa = g_Ax + (size_t)mt*16384;
        const uint8_t* sb = g_Bx + (size_t)nt*BIMG;
#pragma unroll
        for (int r=0;r<6;r++){
            int idx = r*256 + tid;
            if (idx < 1024) cp_async16(sbase + idx*16, sa + idx*16);
            else            cp_async16(sbase + 16384 + (idx-1024)*16, sb + (idx-1024)*16);
        }
    }
    cp_commit(); cp_wait<0>(); __syncthreads();

    float acc[4][2][4];
#pragma unroll
    for (int i=0;i<4;i++)
#pragma unroll
        for (int j=0;j<2;j++)
#pragma unroll
            for (int c=0;c<4;c++) acc[i][j][c]=0.f;

    int g = lane >> 3, l = lane & 7;
    int a_row = wm*64 + (g&1)*8 + l;
    int a_kb  = (g>>1)*16;
    int b_row = wn*16 + (g>>1)*8 + l;
    int b_kb  = (g&1)*16;

#pragma unroll
    for (int s=0; s<4; s++){
        uint32_t Ah[4][4], Bf[2][2];
        uint32_t a_off = swz128((uint32_t)(a_row*128 + s*32 + a_kb));
        uint32_t b_off = swz128((uint32_t)(b_row*128 + s*32 + b_kb));
#pragma unroll
        for (int mi=0; mi<4; mi++)
            ldsm_x4(Ah[mi][0],Ah[mi][1],Ah[mi][2],Ah[mi][3], sbase + a_off + mi*2048);
        {
            uint32_t r0,r1,r2,r3;
            ldsm_x4(r0,r1,r2,r3, sbase + 16384 + b_off);
            Bf[0][0]=r0; Bf[0][1]=r1; Bf[1][0]=r2; Bf[1][1]=r3;
        }
#pragma unroll
        for (int mi=0; mi<4; mi++)
#pragma unroll
            for (int ni=0; ni<2; ni++)
                mma_fp16(acc[mi][ni], Ah[mi], Bf[ni]);
    }

    int rr = lane>>2, cc = (lane&3)*2;
#pragma unroll
    for (int mi=0; mi<4; mi++){
#pragma unroll
        for (int ni=0; ni<2; ni++){
#pragma unroll
            for (int hh=0; hh<2; hh++){
                int m = mt*128 + wm*64 + mi*16 + hh*8 + rr;
                int n = nt*64 + wn*16 + ni*8 + cc;
                int gate = n>>9, j = n&511;
                float v0 = acc[mi][ni][hh*2+0];
                float v1 = acc[mi][ni][hh*2+1];
                if (j+1 < 500){
                    float b0 = bih[gate*500+j]   + (gate<2 ? bhh[gate*500+j]   : 0.f);
                    float b1 = bih[gate*500+j+1] + (gate<2 ? bhh[gate*500+j+1] : 0.f);
                    v0 += b0; v1 += b1;
                }
                *(__half2*)&g_Gx[(size_t)m*NG + n] = __floats2half2_rn(v0, v1);
            }
        }
    }
}

// ----------------------------- persistent stepped kernel ---------------------
__global__ __launch_bounds__(256,2)
void gru_persist(const float* __restrict__ eps,
                 const float* __restrict__ Wihp,
                 const float* __restrict__ bihp, const float* __restrict__ bhhp,
                 const float* __restrict__ bhhq,
                 const float* __restrict__ Wqm, const float* __restrict__ bqm,
                 const float* __restrict__ Wqs, const float* __restrict__ bqs,
                 const float* __restrict__ fw, const float* __restrict__ fb,
                 float* __restrict__ out_z, float* __restrict__ out_mu,
                 float* __restrict__ out_std, float* __restrict__ out_ld){
    int role = blockIdx.y >> 4;
    int gru  = role ? 0 : 1;            // 1 = p, 0 = q
    int nt = blockIdx.x, mt = blockIdx.y & 15;

    extern __shared__ uint8_t smem_raw[];
    uint8_t* tiles = (uint8_t*)(((uintptr_t)smem_raw + 1023) & ~(uintptr_t)1023);
    uint32_t sbase = smem_u32(tiles);
    float* zzS  = (float*)(tiles + 65536);   // p: [64][17] per-step
    float* wpS  = (float*)(tiles + 69888);   // p: [16][192] static
    float* bspS = (float*)(tiles + 82176);   // p: [4][64]  static
    float* WzS  = (float*)(tiles + 83200);   // p: [16][32] static
    float* bnnS = (float*)(tiles + 65536);   // q: [64]     static
    float* WqS  = (float*)(tiles + 65792);   // q: [64][32] static

    int tid = threadIdx.x, wid = tid>>5, lane = tid&31;
    int wm = wid & 1, wn = wid >> 1;

    if (!gru){
        if (tid < 64){
            int j = nt*64 + tid;
            bnnS[tid] = (j < 500) ? bhhq[1000 + j] : 0.f;
        }
        for (int idx = tid; idx < 64*32; idx += 256){
            int j = idx >> 5, o = idx & 31;
            int gj = nt*64 + j;
            float v = 0.f;
            if (gj < H_)
                v = (o < 16) ? Wqm[o*(H_+ZD_) + gj] : Wqs[(o-16)*(H_+ZD_) + gj];
            WqS[j*32+o] = v;
        }
    } else {
        for (int idx = tid; idx < ZD_*192; idx += 256){
            int d = idx & 15, col = idx >> 4;
            int gg = col >> 6, jj = col & 63;
            int j = nt*64 + jj;
            wpS[d*192 + col] = (j < 500) ? Wihp[((size_t)(gg*500 + j))*ZD_ + d] : 0.f;
        }
        {
            int q4 = tid >> 6, jj = tid & 63;
            int j = nt*64 + jj;
            float v = 0.f;
            if (j < 500){
                if (q4 == 0) v = bihp[j]       + bhhp[j];
                else if (q4 == 1) v = bihp[500+j]  + bhhp[500+j];
                else if (q4 == 2) v = bihp[1000+j];
                else v = bhhp[1000+j];
            }
            bspS[q4*64 + jj] = v;
        }
        for (int idx = tid; idx < 16*32; idx += 256){
            int d = idx >> 5, o = idx & 31;
            WzS[idx] = (o < 16) ? Wqm[o*(H_+ZD_) + H_ + d]
                                : Wqs[(o-16)*(H_+ZD_) + H_ + d];
        }
    }
    __syncthreads();

    int g = lane >> 3, l = lane & 7;
    int a_row = wm*32 + (g&1)*8 + l;
    int a_kb  = (g>>1)*16;
    int b_row = wn*16 + (g>>1)*8 + l;
    int b_kb  = (g&1)*16;
    int rr = lane>>2, cc = (lane&3)*2;

    unsigned gen = 0;

    for (int it = -1; it < T_; ++it){
        int t = gru ? it : (it + 1);
        bool active = gru ? (it >= 0) : (it + 1 < T_);
        if (active){
            int par_w = t & 1;
            int par_r = par_w ^ 1;

            auto copy_chunk = [&](int ch, int buf){
                const uint8_t* srcs[4] = {
                    g_Ah + a_img(gru,par_r,mt,ch),
                    g_Bw + b_img(gru,nt,0,ch), g_Bw + b_img(gru,nt,1,ch), g_Bw + b_img(gru,nt,2,ch)
                };
                uint32_t dbase = sbase + buf*32768;
#pragma unroll
                for (int r=0;r<8;r++){
                    int idx = r*256 + tid;
                    int img = idx >> 9;
                    int off = (idx & 511)*16;
                    cp_async16(dbase + img*8192 + off, srcs[img] + off);
                }
            };

            copy_chunk(0,0); cp_commit();

            if (gru){
                float* zpS = (float*)(tiles + 32768);
                float* muS = (float*)(tiles + 36864);
                float* sdS = (float*)(tiles + 40960);
                for (int idx = tid; idx < 64*16; idx += 256){
                    int r = idx >> 4, d = idx & 15;
                    zpS[idx] = (t==0) ? 0.f : out_z[((size_t)(mt*64+r)*T_ + (t-1))*ZD_ + d];
                }
                __syncthreads();
                for (int idx = tid; idx < 64*32; idx += 256){
                    int b = idx >> 5, o = idx & 31;
                    int gb = mt*64 + b;
                    float s = 0.f;
#pragma unroll
                    for (int q8 = 0; q8 < NT_G; q8++) s += g_part[t&1][q8][gb][o];
#pragma unroll
                    for (int d = 0; d < ZD_; d++) s = fmaf(zpS[b*16+d], WzS[d*32+o], s);
                    if (o < 16){
                        float mu = s + bqm[o];
                        muS[b*16+o] = mu;
                        if (nt == 0) out_mu[((size_t)gb*T_+t)*ZD_+o] = mu;
                    } else {
                        int oj = o - 16;
                        float sd = softplusf_(s + bqs[oj]) + 1e-4f;
                        sdS[b*16+oj] = sd;
                        if (nt == 0) out_std[((size_t)gb*T_+t)*ZD_+oj] = sd;
                    }
                }
                __syncthreads();
                if (tid < 64){
                    int b = tid, gb = mt*64 + b;
                    float z[ZD_];
#pragma unroll
                    for (int d=0; d<ZD_; d++)
                        z[d] = muS[b*16+d] + eps[((size_t)gb*T_+t)*ZD_+d]*sdS[b*16+d];
                    float ld = 0.f;
#pragma unroll
                    for (int k=0;k<L_;k++){
                        float dot = 0.f;
                        for (int i=0;i<ZD_;i++) dot = fmaf(z[i], fw[k*ZD_+i], dot);
                        float hh = tanhf(dot + fb[k]);
                        float psiu = 0.f;
                        for (int i=0;i<ZD_;i++){
                            z[i] += g_uhat[k*ZD_+i]*hh;
                            psiu = fmaf((1.f - hh*hh)*fw[k*ZD_+i], g_uhat[k*ZD_+i], psiu);
                        }
                        ld += logf(fabsf(1.f + psiu) + 1e-6f);
                    }
#pragma unroll
                    for (int d=0; d<ZD_; d++) zzS[b*17+d] = z[d];
                    if (nt == 0){
#pragma unroll
                        for (int d=0; d<ZD_; d++) out_z[((size_t)gb*T_+t)*ZD_+d] = z[d];
                        out_ld[gb] += ld;
                    }
                }
            }
            __syncthreads();

            float acc[3][2][2][4];
#pragma unroll
            for (int a=0;a<3;a++)
#pragma unroll
                for (int i=0;i<2;i++)
#pragma unroll
                    for (int j=0;j<2;j++)
#pragma unroll
                        for (int c=0;c<4;c++) acc[a][i][j][c]=0.f;

            for (int ch=0; ch<CH_; ch++){
                if (ch+1 < CH_){ copy_chunk(ch+1,(ch+1)&1); cp_commit(); cp_wait<1>(); }
                else cp_wait<0>();
                __syncthreads();

                uint32_t Ahi_b = sbase + (ch&1)*32768;
                uint32_t Bb    = Ahi_b + 8192;

#pragma unroll
                for (int s=0; s<4; s++){
                    uint32_t Ah[2][4], Bf[3][2][2];
                    uint32_t a_off = swz128((uint32_t)(a_row*128 + s*32 + a_kb));
                    uint32_t b_off = swz128((uint32_t)(b_row*128 + s*32 + b_kb));
#pragma unroll
                    for (int mi=0; mi<2; mi++)
                        ldsm_x4(Ah[mi][0],Ah[mi][1],Ah[mi][2],Ah[mi][3], Ahi_b + a_off + mi*2048);
#pragma unroll
                    for (int g3=0; g3<3; g3++){
                        uint32_t r0,r1,r2,r3;
                        ldsm_x4(r0,r1,r2,r3, Bb + g3*8192 + b_off);
                        Bf[g3][0][0]=r0; Bf[g3][0][1]=r1; Bf[g3][1][0]=r2; Bf[g3][1][1]=r3;
                    }
#pragma unroll
                    for (int g3=0; g3<3; g3++)
#pragma unroll
                        for (int mi=0; mi<2; mi++)
#pragma unroll
                            for (int ni=0; ni<2; ni++)
                                mma_fp16(acc[g3][mi][ni], Ah[mi], Bf[g3][ni]);
                }
                __syncthreads();
            }

            // -------- epilogue: GRU combine in registers --------
            float* hqS = (float*)tiles;              // q: [64][65]
#pragma unroll
            for (int mi=0; mi<2; mi++){
#pragma unroll
                for (int hh=0; hh<2; hh++){
                    int mrow = wm*32 + mi*16 + hh*8 + rr;
                    int b = mt*64 + mrow;
                    float zr[ZD_];
                    if (gru){
#pragma unroll
                        for (int d=0; d<ZD_; d++) zr[d] = zzS[mrow*17 + d];
                    }
#pragma unroll
                    for (int ni=0; ni<2; ni++){
                        int jj = wn*16 + ni*8 + cc;
                        int j = nt*64 + jj;
                        if (j >= 500){
                            if (!gru){ hqS[mrow*65+jj] = 0.f; hqS[mrow*65+jj+1] = 0.f; }
                            continue;
                        }
                        float xw0[3], xw1[3];
                        if (!gru){
                            size_t base = ((size_t)b*T_ + t)*NG + j;
#pragma unroll
                            for (int g3=0; g3<3; g3++){
                                __half2 hv = *(const __half2*)&g_Gx[base + g3*512];
                                xw0[g3] = __low2float(hv);
                                xw1[g3] = __high2float(hv);
                            }
                        } else {
#pragma unroll
                            for (int g3=0; g3<3; g3++){
                                float s0 = bspS[g3*64 + jj];
                                float s1 = bspS[g3*64 + jj + 1];
#pragma unroll
                                for (int d=0; d<ZD_; d++){
                                    float zv = zr[d];
                                    s0 = fmaf(zv, wpS[d*192 + g3*64 + jj],     s0);
                                    s1 = fmaf(zv, wpS[d*192 + g3*64 + jj + 1], s1);
                                }
                                xw0[g3] = s0; xw1[g3] = s1;
                            }
                        }
                        float bn0 = gru ? bspS[3*64 + jj]     : bnnS[jj];
                        float bn1 = gru ? bspS[3*64 + jj + 1] : bnnS[jj + 1];
                        float aR0 = acc[0][mi][ni][hh*2+0], aR1 = acc[0][mi][ni][hh*2+1];
                        float aZ0 = acc[1][mi][ni][hh*2+0], aZ1 = acc[1][mi][ni][hh*2+1];
                        float aN0 = acc[2][mi][ni][hh*2+0], aN1 = acc[2][mi][ni][hh*2+1];

                        float2 hp = *(float2*)&g_h[(size_t)(gru*1024 + b)*HP + j];
                        float r0 = sigmoidf_(xw0[0] + aR0);
                        float r1 = sigmoidf_(xw1[0] + aR1);
                        float z0 = sigmoidf_(xw0[1] + aZ0);
                        float z1 = sigmoidf_(xw1[1] + aZ1);
                        float n0 = tanhf(xw0[2] + r0*(aN0 + bn0));
                        float n1 = tanhf(xw1[2] + r1*(aN1 + bn1));
                        float h0 = (1.f - z0)*n0 + z0*hp.x;
                        float h1 = (1.f - z1)*n1 + z1*hp.y;

                        *(float2*)&g_h[(size_t)(gru*1024 + b)*HP + j] = make_float2(h0, h1);

                        __half2 hi2 = __floats2half2_rn(h0, h1);
                        uint32_t sw = swz128((uint32_t)(mrow*128 + (j&63)*2));
                        *(__half2*)(g_Ah + a_img(gru, par_w, mt, j>>6) + sw) = hi2;

                        if (gru){
                            *(float2*)&g_hist[((size_t)b*T_ + t)*HP + j] = make_float2(h0, h1);
                        } else {
                            hqS[mrow*65+jj]   = h0;
                            hqS[mrow*65+jj+1] = h1;
                        }
                    }
                }
            }

            // -------- q role: mu/std partials for step t --------
            if (!gru){
                __syncthreads();
                for (int idx = tid; idx < 64*32; idx += 256){
                    int b = idx >> 5, o = idx & 31;
                    float s = 0.f;
#pragma unroll
                    for (int j=0;j<64;j++)
                        s = fmaf(hqS[b*65+j], WqS[j*32+o], s);
                    g_part[t&1][nt][mt*64+b][o] = s;
                }
            }
        }
        grid_barrier(gen);
    }
}

// ----------------------------- post-loop: all reconstructions ----------------
__global__ __launch_bounds__(256)
void recon_all(const float* __restrict__ Wpm, const float* __restrict__ bpm,
               const float* __restrict__ Wps, const float* __restrict__ bps,
               float* __restrict__ out_rm, float* __restrict__ out_rs){
    extern __shared__ float hs[];    // [RROWS][HP]
    int m0 = blockIdx.x * RROWS;
    int tid = threadIdx.x, w = tid>>5, lane = tid&31;
#pragma unroll
    for (int k=0;k<RROWS*128/256;k++){
        int idx = k*256 + tid;
        int r = idx >> 7, q4 = idx & 127;
        ((float4*)&hs[r*HP])[q4] = ((const float4*)&g_hist[(size_t)(m0+r)*HP])[q4];
    }
    __syncthreads();
    for (int o = w; o < 2*XD_; o += 8){
        int d = (o < XD_) ? o : o - XD_;
        const float* Wrow = ((o < XD_) ? Wpm : Wps) + (size_t)d*H_;
        for (int r=0;r<RROWS;r++){
            float acc = 0.f;
            for (int i=lane; i<H_; i+=32) acc = fmaf(hs[r*HP+i], Wrow[i], acc);
#pragma unroll
            for (int off=16; off; off>>=1) acc += __shfl_down_sync(0xFFFFFFFFu, acc, off);
            if (lane == 0){
                size_t oidx = (size_t)(m0+r)*XD_ + d;
                if (o < XD_) out_rm[oidx] = acc + bpm[d];
                else         out_rs[oidx] = softplusf_(acc + bps[d]) + 1e-4f;
            }
        }
    }
}

// ----------------------------- launcher --------------------------------------
extern "C" void kernel_launch(void* const* d_in, const int* in_sizes, int n_in,
                              void* d_out, int out_size){
    const float* x     = (const float*)d_in[0];
    const float* eps   = (const float*)d_in[1];
    const float* Wih_q = (const float*)d_in[2];
    const float* Whh_q = (const float*)d_in[3];
    const float* bih_q = (const float*)d_in[4];
    const float* bhh_q = (const float*)d_in[5];
    const float* Wqm   = (const float*)d_in[6];
    const float* bqm   = (const float*)d_in[7];
    const float* Wqs   = (const float*)d_in[8];
    const float* bqs   = (const float*)d_in[9];
    const float* Wih_p = (const float*)d_in[10];
    const float* Whh_p = (const float*)d_in[11];
    const float* bih_p = (const float*)d_in[12];
    const float* bhh_p = (const float*)d_in[13];
    const float* Wpm   = (const float*)d_in[14];
    const float* bpm   = (const float*)d_in[15];
    const float* Wps   = (const float*)d_in[16];
    const float* bps   = (const float*)d_in[17];
    const float* fu    = (const float*)d_in[18];
    const float* fw    = (const float*)d_in[19];
    const float* fb    = (const float*)d_in[20];

    float* out = (float*)d_out;
    float* out_rm  = out;
    float* out_rs  = out_rm  + (size_t)B_*T_*XD_;
    float* out_z   = out_rs  + (size_t)B_*T_*XD_;
    float* out_mu  = out_z   + (size_t)B_*T_*ZD_;
    float* out_std = out_mu  + (size_t)B_*T_*ZD_;
    float* out_ld  = out_std + (size_t)B_*T_*ZD_;

    cudaFuncSetAttribute(gru_persist, cudaFuncAttributeMaxDynamicSharedMemorySize, SMEM_P);
    cudaFuncSetAttribute(gx_gemm,     cudaFuncAttributeMaxDynamicSharedMemorySize, SMEM_GX);
    cudaFuncSetAttribute(recon_all,   cudaFuncAttributeMaxDynamicSharedMemorySize, SMEM_RC);

    init_kernel<<<1024,256>>>(out_ld, fu, fw);
    stage_whh<<<(2*G3H*H_+255)/256,256>>>(Whh_q, Whh_p);
    stage_x_wih<<<(B_*T_*XD_ + G3H*XD_ + 255)/256,256>>>(x, Wih_q);
    gx_gemm<<<dim3(GXNT, GXMT),256,SMEM_GX>>>(bih_q, bhh_q);

    dim3 pq_grid(NT_G, 32);   // 8 x 32 = 256 CTAs, 2/SM -> all resident
    gru_persist<<<pq_grid,256,SMEM_P>>>(eps, Wih_p, bih_p, bhh_p, bhh_q,
                                        Wqm, bqm, Wqs, bqs, fw, fb,
                                        out_z, out_mu, out_std, out_ld);

    recon_all<<<(B_*T_)/RROWS,256,SMEM_RC>>>(Wpm, bpm, Wps, bps, out_rm, out_rs);
}

// round 15
// speedup vs baseline: 1.2575x; 1.0619x over previous
#include <cuda_runtime.h>
#include <cuda_fp16.h>
#include <math.h>
#include <stdint.h>

#define B_   1024
#define T_   100
#define XD_  38
#define H_   500
#define ZD_  16
#define L_   3
#define G3H  1500
#define HP   512
#define NG   1536
#define MT_G 16
#define NT_G 8
#define CH_  8
#define BIMG 8192
#define GXMT 800
#define GXNT 24
#define RROWS 32
#define NCTA_P 256
#define SMEM_GX  25600
#define SMEM_RC  65536

// ----------------------------- device scratch --------------------------------
__device__ __align__(1024) float   g_h[(size_t)2*B_*HP];
// A fragments: [gru][par][mt][ch][s][wm][mi] x 512B
__device__ __align__(1024) uint8_t g_Afrag[(size_t)2*2*MT_G*CH_*4*2*2*512];
// B fragments: [gru][nt][wn][gate][ch][s] x 512B
__device__ __align__(1024) uint8_t g_Bfrag[(size_t)2*NT_G*4*3*CH_*4*512];
__device__ __align__(1024) uint8_t g_Ax[(size_t)GXMT*16384];
__device__ __align__(1024) uint8_t g_Bx[(size_t)GXNT*BIMG];
__device__ __align__(1024) __half  g_Gx[(size_t)B_*T_*NG];
__device__ __align__(1024) float   g_hist[(size_t)B_*T_*HP];
__device__ float g_part[2][NT_G][B_][32];
__device__ float g_uhat[L_*ZD_];
__device__ unsigned g_bar_count;
__device__ volatile unsigned g_bar_gen;

// ----------------------------- helpers ---------------------------------------
__device__ __forceinline__ float sigmoidf_(float x){ return fmaf(0.5f, tanhf(0.5f*x), 0.5f); }
__device__ __forceinline__ float softplusf_(float x){ return (x>20.0f)? x : log1pf(expf(x)); }
__device__ __forceinline__ uint32_t swz128(uint32_t off){ return off ^ ((off>>3)&0x70); }

__device__ __forceinline__ size_t afrag(int gru,int par,int mt,int ch,int s,int wm,int mi){
    return ((((((size_t)gru*2 + par)*MT_G + mt)*CH_ + ch)*4 + s)*2 + wm)*2*512 + (size_t)mi*512;
}
__device__ __forceinline__ size_t bfrag(int gru,int nt,int wn,int gate,int ch,int s){
    return (((((size_t)gru*NT_G + nt)*4 + wn)*3 + gate)*CH_*4 + (size_t)ch*4 + s)*512;
}
__device__ __forceinline__ uint32_t smem_u32(const void* p){
    uint32_t a;
    asm("{ .reg .u64 t; cvta.to.shared.u64 t, %1; cvt.u32.u64 %0, t; }" : "=r"(a) : "l"(p));
    return a;
}
__device__ __forceinline__ void cp_async16(uint32_t dst, const void* src){
    asm volatile("cp.async.cg.shared.global [%0], [%1], 16;" :: "r"(dst), "l"(src));
}
__device__ __forceinline__ void cp_commit(){ asm volatile("cp.async.commit_group;" ::: "memory"); }
template<int N>
__device__ __forceinline__ void cp_wait(){ asm volatile("cp.async.wait_group %0;" :: "n"(N) : "memory"); }
__device__ __forceinline__ void ldsm_x4(uint32_t& r0, uint32_t& r1, uint32_t& r2, uint32_t& r3, uint32_t addr){
    asm volatile("ldmatrix.sync.aligned.m8n8.x4.shared.b16 {%0,%1,%2,%3}, [%4];"
                 : "=r"(r0), "=r"(r1), "=r"(r2), "=r"(r3) : "r"(addr));
}
__device__ __forceinline__ void mma_fp16(float* c, const uint32_t* a, const uint32_t* b){
    asm volatile("mma.sync.aligned.m16n8k16.row.col.f32.f16.f16.f32 "
                 "{%0,%1,%2,%3}, {%4,%5,%6,%7}, {%8,%9}, {%0,%1,%2,%3};"
                 : "+f"(c[0]), "+f"(c[1]), "+f"(c[2]), "+f"(c[3])
                 : "r"(a[0]), "r"(a[1]), "r"(a[2]), "r"(a[3]), "r"(b[0]), "r"(b[1]));
}
__device__ __forceinline__ void grid_barrier(unsigned &gen){
    __syncthreads();
    gen++;
    if (threadIdx.x == 0){
        __threadfence();
        unsigned prev = atomicAdd(&g_bar_count, 1u);
        if (prev == gen*NCTA_P - 1u){
            __threadfence();
            g_bar_gen = gen;
        } else {
            while (g_bar_gen < gen) __nanosleep(64);
        }
    }
    __syncthreads();
    __threadfence();
}

// ----------------------------- setup launch 1: init --------------------------
__global__ void init_kernel(float* __restrict__ out_ld,
                            const float* __restrict__ fu, const float* __restrict__ fw){
    size_t i = (size_t)blockIdx.x*blockDim.x + threadIdx.x;
    size_t stride = (size_t)gridDim.x*blockDim.x;
    float4* h4 = (float4*)g_h;
    for (size_t k=i; k<sizeof(g_h)/16;  k+=stride) h4[k] = make_float4(0,0,0,0);
    uint4* p;
    p = (uint4*)g_Afrag; for (size_t k=i; k<sizeof(g_Afrag)/16; k+=stride) p[k] = make_uint4(0,0,0,0);
    p = (uint4*)g_Bfrag; for (size_t k=i; k<sizeof(g_Bfrag)/16; k+=stride) p[k] = make_uint4(0,0,0,0);
    p = (uint4*)g_Ax;    for (size_t k=i; k<sizeof(g_Ax)/16;    k+=stride) p[k] = make_uint4(0,0,0,0);
    p = (uint4*)g_Bx;    for (size_t k=i; k<sizeof(g_Bx)/16;    k+=stride) p[k] = make_uint4(0,0,0,0);
    for (size_t k=i; k<B_; k+=stride) out_ld[k]=0.f;
    if (i == 0){ g_bar_count = 0; g_bar_gen = 0; }
    if (i < L_){
        int k = (int)i;
        float wu=0.f, ww=0.f;
        for (int j=0;j<ZD_;j++){ wu += fw[k*ZD_+j]*fu[k*ZD_+j]; ww += fw[k*ZD_+j]*fw[k*ZD_+j]; }
        float m = -1.0f + softplusf_(wu);
        float scale = (m - wu)/(ww + 1e-6f);
        for (int j=0;j<ZD_;j++) g_uhat[k*ZD_+j] = fu[k*ZD_+j] + scale*fw[k*ZD_+j];
    }
}

// ----------------------------- setup launch 2: stage Whh into B frags --------
__global__ void stage_whh(const float* __restrict__ Wq, const float* __restrict__ Wp){
    int idx = blockIdx.x*blockDim.x + threadIdx.x;
    if (idx >= 2*G3H*H_) return;
    int gru = idx / (G3H*H_);
    int rem = idx - gru*(G3H*H_);
    int n = rem / H_, k = rem - n*H_;
    float v = (gru ? Wp : Wq)[n*H_ + k];
    int gate = n / 500, j = n - gate*500;
    int nt = j>>6, jj = j&63, wn = jj>>4, r = jj&15;
    int ni = r>>3, nn = r&7;
    int ch = k>>6, kc = k&63, s = kc>>4, kk = kc&15;
    uint32_t lane = nn*4 + ((kk&7)>>1);
    uint32_t reg  = ni*2 + (kk>>3);
    uint32_t half = kk&1;
    *(__half*)(g_Bfrag + bfrag(gru,nt,wn,gate,ch,s) + lane*16 + reg*4 + half*2) = __float2half_rn(v);
}

// ----------------------------- setup launch 3: stage x + Wih_q (gx path) -----
__global__ void stage_x_wih(const float* __restrict__ x, const float* __restrict__ Wih_q){
    int idx = blockIdx.x*blockDim.x + threadIdx.x;
    const int NX = B_*T_*XD_;
    if (idx < NX){
        int m = idx / XD_, d = idx - m*XD_;
        int mt = m>>7, r = m&127;
        uint32_t sw = swz128((uint32_t)(r*128 + d*2));
        *(__half*)(g_Ax + (size_t)mt*16384 + sw) = __float2half_rn(x[idx]);
    } else if (idx < NX + G3H*XD_){
        int e = idx - NX;
        int n = e / XD_, d = e - n*XD_;
        int gate = n / 500, j = n - gate*500;
        int ni = gate*512 + j;
        int nt = ni>>6, r = ni&63;
        *(__half*)(g_Bx + (size_t)nt*BIMG + swz128((uint32_t)(r*128 + d*2))) =
            __float2half_rn(Wih_q[n*XD_ + d]);
    }
}

// ----------------------------- setup launch 4: Gx = x @ Wih_q^T + bias -------
__global__ __launch_bounds__(256)
void gx_gemm(const float* __restrict__ bih, const float* __restrict__ bhh){
    extern __shared__ uint8_t smem_raw[];
    uint8_t* tiles = (uint8_t*)(((uintptr_t)smem_raw + 1023) & ~(uintptr_t)1023);
    uint32_t sbase = smem_u32(tiles);
    int tid = threadIdx.x, wid = tid>>5, lane = tid&31;
    int nt = blockIdx.x, mt = blockIdx.y;
    int wm = wid & 1, wn = wid >> 1;

    {
        const uint8_t* sa = g_Ax + (size_t)mt*16384;
        const uint8_t* sb = g_Bx + (size_t)nt*BIMG;
#pragma unroll
        for (int r=0;r<6;r++){
            int idx = r*256 + tid;
            if (idx < 1024) cp_async16(sbase + idx*16, sa + idx*16);
            else            cp_async16(sbase + 16384 + (idx-1024)*16, sb + (idx-1024)*16);
        }
    }
    cp_commit(); cp_wait<0>(); __syncthreads();

    float acc[4][2][4];
#pragma unroll
    for (int i=0;i<4;i++)
#pragma unroll
        for (int j=0;j<2;j++)
#pragma unroll
            for (int c=0;c<4;c++) acc[i][j][c]=0.f;

    int g = lane >> 3, l = lane & 7;
    int a_row = wm*64 + (g&1)*8 + l;
    int a_kb  = (g>>1)*16;
    int b_row = wn*16 + (g>>1)*8 + l;
    int b_kb  = (g&1)*16;

#pragma unroll
    for (int s=0; s<4; s++){
        uint32_t Ah[4][4], Bf[2][2];
        uint32_t a_off = swz128((uint32_t)(a_row*128 + s*32 + a_kb));
        uint32_t b_off = swz128((uint32_t)(b_row*128 + s*32 + b_kb));
#pragma unroll
        for (int mi=0; mi<4; mi++)
            ldsm_x4(Ah[mi][0],Ah[mi][1],Ah[mi][2],Ah[mi][3], sbase + a_off + mi*2048);
        {
            uint32_t r0,r1,r2,r3;
            ldsm_x4(r0,r1,r2,r3, sbase + 16384 + b_off);
            Bf[0][0]=r0; Bf[0][1]=r1; Bf[1][0]=r2; Bf[1][1]=r3;
        }
#pragma unroll
        for (int mi=0; mi<4; mi++)
#pragma unroll
            for (int ni=0; ni<2; ni++)
                mma_fp16(acc[mi][ni], Ah[mi], Bf[ni]);
    }

    int rr = lane>>2, cc = (lane&3)*2;
#pragma unroll
    for (int mi=0; mi<4; mi++){
#pragma unroll
        for (int ni=0; ni<2; ni++){
#pragma unroll
            for (int hh=0; hh<2; hh++){
                int m = mt*128 + wm*64 + mi*16 + hh*8 + rr;
                int n = nt*64 + wn*16 + ni*8 + cc;
                int gate = n>>9, j = n&511;
                float v0 = acc[mi][ni][hh*2+0];
                float v1 = acc[mi][ni][hh*2+1];
                if (j+1 < 500){
                    float b0 = bih[gate*500+j]   + (gate<2 ? bhh[gate*500+j]   : 0.f);
                    float b1 = bih[gate*500+j+1] + (gate<2 ? bhh[gate*500+j+1] : 0.f);
                    v0 += b0; v1 += b1;
                }
                *(__half2*)&g_Gx[(size_t)m*NG + n] = __floats2half2_rn(v0, v1);
            }
        }
    }
}

// ----------------------------- persistent stepped kernel ---------------------
// Fragment-direct GEMM: A/B operands fetched with LDG.128 straight into mma
// register layout. No smem tiles, no cp.async, no ldsm in the mainloop.
__global__ __launch_bounds__(256,2)
void gru_persist(const float* __restrict__ eps,
                 const float* __restrict__ Wihp,
                 const float* __restrict__ bihp, const float* __restrict__ bhhp,
                 const float* __restrict__ bhhq,
                 const float* __restrict__ Wqm, const float* __restrict__ bqm,
                 const float* __restrict__ Wqs, const float* __restrict__ bqs,
                 const float* __restrict__ fw, const float* __restrict__ fb,
                 float* __restrict__ out_z, float* __restrict__ out_mu,
                 float* __restrict__ out_std, float* __restrict__ out_ld){
    int role = blockIdx.y >> 4;
    int gru  = role ? 0 : 1;            // 1 = p, 0 = q
    int nt = blockIdx.x, mt = blockIdx.y & 15;

    __shared__ __align__(16) float smf[8192];   // 32 KB role-union scratch
    // p layout
    float* zzS  = smf;           // [64][17]
    float* wpS  = smf + 1088;    // [16][192]
    float* bspS = smf + 4160;    // [4][64]
    float* WzS  = smf + 4416;    // [16][32]
    float* zpS  = smf + 4928;    // [64][16]
    float* muS  = smf + 5952;    // [64][16]
    float* sdS  = smf + 6976;    // [64][16]
    // q layout
    float* bnnS = smf;           // [64]
    float* WqS  = smf + 64;      // [64][32]
    float* hqS  = smf + 2112;    // [64][65]

    int tid = threadIdx.x, wid = tid>>5, lane = tid&31;
    int wm = wid & 1, wn = wid >> 1;

    // ---- one-time staging of time-invariant data ----
    if (!gru){
        if (tid < 64){
            int j = nt*64 + tid;
            bnnS[tid] = (j < 500) ? bhhq[1000 + j] : 0.f;
        }
        for (int idx = tid; idx < 64*32; idx += 256){
            int j = idx >> 5, o = idx & 31;
            int gj = nt*64 + j;
            float v = 0.f;
            if (gj < H_)
                v = (o < 16) ? Wqm[o*(H_+ZD_) + gj] : Wqs[(o-16)*(H_+ZD_) + gj];
            WqS[j*32+o] = v;
        }
    } else {
        for (int idx = tid; idx < ZD_*192; idx += 256){
            int d = idx & 15, col = idx >> 4;
            int gg = col >> 6, jj = col & 63;
            int j = nt*64 + jj;
            wpS[d*192 + col] = (j < 500) ? Wihp[((size_t)(gg*500 + j))*ZD_ + d] : 0.f;
        }
        {
            int q4 = tid >> 6, jj = tid & 63;
            int j = nt*64 + jj;
            float v = 0.f;
            if (j < 500){
                if (q4 == 0) v = bihp[j]       + bhhp[j];
                else if (q4 == 1) v = bihp[500+j]  + bhhp[500+j];
                else if (q4 == 2) v = bihp[1000+j];
                else v = bhhp[1000+j];
            }
            bspS[q4*64 + jj] = v;
        }
        for (int idx = tid; idx < 16*32; idx += 256){
            int d = idx >> 5, o = idx & 31;
            WzS[idx] = (o < 16) ? Wqm[o*(H_+ZD_) + H_ + d]
                                : Wqs[(o-16)*(H_+ZD_) + H_ + d];
        }
    }
    __syncthreads();

    int rr = lane>>2, cc = (lane&3)*2;
    unsigned gen = 0;

    for (int it = -1; it < T_; ++it){
        int t = gru ? it : (it + 1);
        bool active = gru ? (it >= 0) : (it + 1 < T_);
        if (active){
            int par_w = t & 1;
            int par_r = par_w ^ 1;

            if (gru){
                // ---------- p prologue: z(t) from partials + flows ----------
                for (int idx = tid; idx < 64*16; idx += 256){
                    int r = idx >> 4, d = idx & 15;
                    zpS[idx] = (t==0) ? 0.f : out_z[((size_t)(mt*64+r)*T_ + (t-1))*ZD_ + d];
                }
                __syncthreads();
                for (int idx = tid; idx < 64*32; idx += 256){
                    int b = idx >> 5, o = idx & 31;
                    int gb = mt*64 + b;
                    float s = 0.f;
#pragma unroll
                    for (int q8 = 0; q8 < NT_G; q8++) s += g_part[t&1][q8][gb][o];
#pragma unroll
                    for (int d = 0; d < ZD_; d++) s = fmaf(zpS[b*16+d], WzS[d*32+o], s);
                    if (o < 16){
                        float mu = s + bqm[o];
                        muS[b*16+o] = mu;
                        if (nt == 0) out_mu[((size_t)gb*T_+t)*ZD_+o] = mu;
                    } else {
                        int oj = o - 16;
                        float sd = softplusf_(s + bqs[oj]) + 1e-4f;
                        sdS[b*16+oj] = sd;
                        if (nt == 0) out_std[((size_t)gb*T_+t)*ZD_+oj] = sd;
                    }
                }
                __syncthreads();
                if (tid < 64){
                    int b = tid, gb = mt*64 + b;
                    float z[ZD_];
#pragma unroll
                    for (int d=0; d<ZD_; d++)
                        z[d] = muS[b*16+d] + eps[((size_t)gb*T_+t)*ZD_+d]*sdS[b*16+d];
                    float ld = 0.f;
#pragma unroll
                    for (int k=0;k<L_;k++){
                        float dot = 0.f;
                        for (int i=0;i<ZD_;i++) dot = fmaf(z[i], fw[k*ZD_+i], dot);
                        float hh = tanhf(dot + fb[k]);
                        float psiu = 0.f;
                        for (int i=0;i<ZD_;i++){
                            z[i] += g_uhat[k*ZD_+i]*hh;
                            psiu = fmaf((1.f - hh*hh)*fw[k*ZD_+i], g_uhat[k*ZD_+i], psiu);
                        }
                        ld += logf(fabsf(1.f + psiu) + 1e-6f);
                    }
#pragma unroll
                    for (int d=0; d<ZD_; d++) zzS[b*17+d] = z[d];
                    if (nt == 0){
#pragma unroll
                        for (int d=0; d<ZD_; d++) out_z[((size_t)gb*T_+t)*ZD_+d] = z[d];
                        out_ld[gb] += ld;
                    }
                }
                __syncthreads();
            }

            // ================= fragment-direct GEMM mainloop =================
            float acc[3][2][2][4];
#pragma unroll
            for (int a=0;a<3;a++)
#pragma unroll
                for (int i=0;i<2;i++)
#pragma unroll
                    for (int j=0;j<2;j++)
#pragma unroll
                        for (int c=0;c<4;c++) acc[a][i][j][c]=0.f;

            const uint4* Abase = (const uint4*)(g_Afrag + afrag(gru,par_r,mt,0,0,wm,0) + lane*16);
            const uint4* Bbase = (const uint4*)(g_Bfrag + bfrag(gru,nt,wn,0,0,0) + lane*16);
            // strides in uint4 units: A: mi=32, s=128, ch=512 ; B: s=32, ch=128, gate=1024
            for (int ch=0; ch<CH_; ch++){
#pragma unroll
                for (int s=0; s<4; s++){
                    const uint4* ap = Abase + ch*512 + s*128;
                    const uint4* bp = Bbase + ch*128 + s*32;
                    uint4 av0 = __ldg(ap);
                    uint4 av1 = __ldg(ap + 32);
                    uint4 bv0 = __ldg(bp);
                    uint4 bv1 = __ldg(bp + 1024);
                    uint4 bv2 = __ldg(bp + 2048);
                    uint32_t A0[4] = {av0.x,av0.y,av0.z,av0.w};
                    uint32_t A1[4] = {av1.x,av1.y,av1.z,av1.w};
                    uint32_t B0[2][2] = {{bv0.x,bv0.y},{bv0.z,bv0.w}};
                    uint32_t B1[2][2] = {{bv1.x,bv1.y},{bv1.z,bv1.w}};
                    uint32_t B2[2][2] = {{bv2.x,bv2.y},{bv2.z,bv2.w}};
                    mma_fp16(acc[0][0][0], A0, B0[0]); mma_fp16(acc[0][0][1], A0, B0[1]);
                    mma_fp16(acc[0][1][0], A1, B0[0]); mma_fp16(acc[0][1][1], A1, B0[1]);
                    mma_fp16(acc[1][0][0], A0, B1[0]); mma_fp16(acc[1][0][1], A0, B1[1]);
                    mma_fp16(acc[1][1][0], A1, B1[0]); mma_fp16(acc[1][1][1], A1, B1[1]);
                    mma_fp16(acc[2][0][0], A0, B2[0]); mma_fp16(acc[2][0][1], A0, B2[1]);
                    mma_fp16(acc[2][1][0], A1, B2[0]); mma_fp16(acc[2][1][1], A1, B2[1]);
                }
            }

            // -------- epilogue: GRU combine in registers --------
#pragma unroll
            for (int mi=0; mi<2; mi++){
#pragma unroll
                for (int hh=0; hh<2; hh++){
                    int mrow = wm*32 + mi*16 + hh*8 + rr;
                    int b = mt*64 + mrow;
                    float zr[ZD_];
                    if (gru){
#pragma unroll
                        for (int d=0; d<ZD_; d++) zr[d] = zzS[mrow*17 + d];
                    }
#pragma unroll
                    for (int ni=0; ni<2; ni++){
                        int jj = wn*16 + ni*8 + cc;
                        int j = nt*64 + jj;
                        if (j >= 500){
                            if (!gru){ hqS[mrow*65+jj] = 0.f; hqS[mrow*65+jj+1] = 0.f; }
                            continue;
                        }
                        float xw0[3], xw1[3];
                        if (!gru){
                            size_t base = ((size_t)b*T_ + t)*NG + j;
#pragma unroll
                            for (int g3=0; g3<3; g3++){
                                __half2 hv = *(const __half2*)&g_Gx[base + g3*512];
                                xw0[g3] = __low2float(hv);
                                xw1[g3] = __high2float(hv);
                            }
                        } else {
#pragma unroll
                            for (int g3=0; g3<3; g3++){
                                float s0 = bspS[g3*64 + jj];
                                float s1 = bspS[g3*64 + jj + 1];
#pragma unroll
                                for (int d=0; d<ZD_; d++){
                                    float zv = zr[d];
                                    s0 = fmaf(zv, wpS[d*192 + g3*64 + jj],     s0);
                                    s1 = fmaf(zv, wpS[d*192 + g3*64 + jj + 1], s1);
                                }
                                xw0[g3] = s0; xw1[g3] = s1;
                            }
                        }
                        float bn0 = gru ? bspS[3*64 + jj]     : bnnS[jj];
                        float bn1 = gru ? bspS[3*64 + jj + 1] : bnnS[jj + 1];
                        float aR0 = acc[0][mi][ni][hh*2+0], aR1 = acc[0][mi][ni][hh*2+1];
                        float aZ0 = acc[1][mi][ni][hh*2+0], aZ1 = acc[1][mi][ni][hh*2+1];
                        float aN0 = acc[2][mi][ni][hh*2+0], aN1 = acc[2][mi][ni][hh*2+1];

                        float2 hp = *(float2*)&g_h[(size_t)(gru*1024 + b)*HP + j];
                        float r0 = sigmoidf_(xw0[0] + aR0);
                        float r1 = sigmoidf_(xw1[0] + aR1);
                        float z0 = sigmoidf_(xw0[1] + aZ0);
                        float z1 = sigmoidf_(xw1[1] + aZ1);
                        float n0 = tanhf(xw0[2] + r0*(aN0 + bn0));
                        float n1 = tanhf(xw1[2] + r1*(aN1 + bn1));
                        float h0 = (1.f - z0)*n0 + z0*hp.x;
                        float h1 = (1.f - z1)*n1 + z1*hp.y;

                        *(float2*)&g_h[(size_t)(gru*1024 + b)*HP + j] = make_float2(h0, h1);

                        // write A fragment for next step (canonical m16k16 layout)
                        {
                            __half2 hi2 = __floats2half2_rn(h0, h1);
                            int r16 = mrow & 15;
                            int wmw = mrow >> 5, miw = (mrow >> 4) & 1;
                            int kk = jj & 15, s_w = (jj >> 4) & 3;
                            uint32_t lane_w = (uint32_t)((r16 & 7)*4 + ((kk & 7) >> 1));
                            uint32_t reg_w  = (uint32_t)(((r16 >> 3) & 1) + ((kk >> 3) & 1)*2);
                            *(__half2*)(g_Afrag + afrag(gru, par_w, mt, nt, s_w, wmw, miw)
                                        + lane_w*16 + reg_w*4) = hi2;
                        }

                        if (gru){
                            *(float2*)&g_hist[((size_t)b*T_ + t)*HP + j] = make_float2(h0, h1);
                        } else {
                            hqS[mrow*65+jj]   = h0;
                            hqS[mrow*65+jj+1] = h1;
                        }
                    }
                }
            }

            // -------- q role: mu/std partials for step t --------
            if (!gru){
                __syncthreads();
                for (int idx = tid; idx < 64*32; idx += 256){
                    int b = idx >> 5, o = idx & 31;
                    float s = 0.f;
#pragma unroll
                    for (int j=0;j<64;j++)
                        s = fmaf(hqS[b*65+j], WqS[j*32+o], s);
                    g_part[t&1][nt][mt*64+b][o] = s;
                }
            }
        }
        grid_barrier(gen);
    }
}

// ----------------------------- post-loop: all reconstructions ----------------
__global__ __launch_bounds__(256)
void recon_all(const float* __restrict__ Wpm, const float* __restrict__ bpm,
               const float* __restrict__ Wps, const float* __restrict__ bps,
               float* __restrict__ out_rm, float* __restrict__ out_rs){
    extern __shared__ float hs[];    // [RROWS][HP]
    int m0 = blockIdx.x * RROWS;
    int tid = threadIdx.x, w = tid>>5, lane = tid&31;
#pragma unroll
    for (int k=0;k<RROWS*128/256;k++){
        int idx = k*256 + tid;
        int r = idx >> 7, q4 = idx & 127;
        ((float4*)&hs[r*HP])[q4] = ((const float4*)&g_hist[(size_t)(m0+r)*HP])[q4];
    }
    __syncthreads();
    for (int o = w; o < 2*XD_; o += 8){
        int d = (o < XD_) ? o : o - XD_;
        const float* Wrow = ((o < XD_) ? Wpm : Wps) + (size_t)d*H_;
        for (int r=0;r<RROWS;r++){
            float acc = 0.f;
            for (int i=lane; i<H_; i+=32) acc = fmaf(hs[r*HP+i], Wrow[i], acc);
#pragma unroll
            for (int off=16; off; off>>=1) acc += __shfl_down_sync(0xFFFFFFFFu, acc, off);
            if (lane == 0){
                size_t oidx = (size_t)(m0+r)*XD_ + d;
                if (o < XD_) out_rm[oidx] = acc + bpm[d];
                else         out_rs[oidx] = softplusf_(acc + bps[d]) + 1e-4f;
            }
        }
    }
}

// ----------------------------- launcher --------------------------------------
extern "C" void kernel_launch(void* const* d_in, const int* in_sizes, int n_in,
                              void* d_out, int out_size){
    const float* x     = (const float*)d_in[0];
    const float* eps   = (const float*)d_in[1];
    const float* Wih_q = (const float*)d_in[2];
    const float* Whh_q = (const float*)d_in[3];
    const float* bih_q = (const float*)d_in[4];
    const float* bhh_q = (const float*)d_in[5];
    const float* Wqm   = (const float*)d_in[6];
    const float* bqm   = (const float*)d_in[7];
    const float* Wqs   = (const float*)d_in[8];
    const float* bqs   = (const float*)d_in[9];
    const float* Wih_p = (const float*)d_in[10];
    const float* Whh_p = (const float*)d_in[11];
    const float* bih_p = (const float*)d_in[12];
    const float* bhh_p = (const float*)d_in[13];
    const float* Wpm   = (const float*)d_in[14];
    const float* bpm   = (const float*)d_in[15];
    const float* Wps   = (const float*)d_in[16];
    const float* bps   = (const float*)d_in[17];
    const float* fu    = (const float*)d_in[18];
    const float* fw    = (const float*)d_in[19];
    const float* fb    = (const float*)d_in[20];

    float* out = (float*)d_out;
    float* out_rm  = out;
    float* out_rs  = out_rm  + (size_t)B_*T_*XD_;
    float* out_z   = out_rs  + (size_t)B_*T_*XD_;
    float* out_mu  = out_z   + (size_t)B_*T_*ZD_;
    float* out_std = out_mu  + (size_t)B_*T_*ZD_;
    float* out_ld  = out_std + (size_t)B_*T_*ZD_;

    cudaFuncSetAttribute(gx_gemm,   cudaFuncAttributeMaxDynamicSharedMemorySize, SMEM_GX);
    cudaFuncSetAttribute(recon_all, cudaFuncAttributeMaxDynamicSharedMemorySize, SMEM_RC);

    init_kernel<<<1024,256>>>(out_ld, fu, fw);
    stage_whh<<<(2*G3H*H_+255)/256,256>>>(Whh_q, Whh_p);
    stage_x_wih<<<(B_*T_*XD_ + G3H*XD_ + 255)/256,256>>>(x, Wih_q);
    gx_gemm<<<dim3(GXNT, GXMT),256,SMEM_GX>>>(bih_q, bhh_q);

    dim3 pq_grid(NT_G, 32);   // 8 x 32 = 256 CTAs, min 2/SM -> all resident
    gru_persist<<<pq_grid,256>>>(eps, Wih_p, bih_p, bhh_p, bhh_q,
                                 Wqm, bqm, Wqs, bqs, fw, fb,
                                 out_z, out_mu, out_std, out_ld);

    recon_all<<<(B_*T_)/RROWS,256,SMEM_RC>>>(Wpm, bpm, Wps, bps, out_rm, out_rs);
}